// round 1
// baseline (speedup 1.0000x reference)
#include <cuda_runtime.h>
#include <math.h>

#define BATCH   8
#define TSEQ    2048
#define CDIM    1024
#define HDIM    128
#define BT_TOTAL (BATCH*TSEQ)   // 16384
#define BM      64
#define BN      64

// Scratch for q,k,v projections (no cudaMalloc allowed).
__device__ float g_q[BT_TOTAL * HDIM];
__device__ float g_k[BT_TOTAL * HDIM];
__device__ float g_v[BT_TOTAL * HDIM];

// ---------------------------------------------------------------------------
// Projection GEMM: out[m][n] = sum_k x[m][k] * W[k][n]
// M=16384, K=1024, N=128. blockIdx.y selects Wq/Wk/Wv.
// Tile: BMp=64 rows, full N=128, BK=32. 256 threads, 4x8 microtile/thread.
// ---------------------------------------------------------------------------
__global__ __launch_bounds__(256) void proj_kernel(
    const float* __restrict__ x,
    const float* __restrict__ Wq,
    const float* __restrict__ Wk,
    const float* __restrict__ Wv)
{
    __shared__ float xs[64][33];    // padded to kill conflicts on column reads
    __shared__ float ws[32][128];

    const float* W   = (blockIdx.y == 0) ? Wq : (blockIdx.y == 1 ? Wk : Wv);
    float*       outp= (blockIdx.y == 0) ? g_q : (blockIdx.y == 1 ? g_k : g_v);

    const int m0  = blockIdx.x * 64;
    const int tid = threadIdx.x;
    const int tx  = tid & 15;   // cols tx*8 .. +7
    const int ty  = tid >> 4;   // rows ty*4 .. +3

    float acc[4][8];
#pragma unroll
    for (int i = 0; i < 4; i++)
#pragma unroll
        for (int j = 0; j < 8; j++) acc[i][j] = 0.f;

    for (int k0 = 0; k0 < CDIM; k0 += 32) {
        // load x tile 64x32 (512 float4s, coalesced: f4 = tid + 256*i)
#pragma unroll
        for (int i = 0; i < 2; i++) {
            int f4 = tid + 256 * i;          // 0..511
            int r  = f4 >> 3;                // /8 -> row
            int c4 = f4 & 7;
            float4 v = *(const float4*)&x[(size_t)(m0 + r) * CDIM + k0 + c4 * 4];
            xs[r][c4 * 4 + 0] = v.x; xs[r][c4 * 4 + 1] = v.y;
            xs[r][c4 * 4 + 2] = v.z; xs[r][c4 * 4 + 3] = v.w;
        }
        // load W tile 32x128 (1024 float4s)
#pragma unroll
        for (int i = 0; i < 4; i++) {
            int f4 = tid + 256 * i;          // 0..1023
            int r  = f4 >> 5;
            int c4 = f4 & 31;
            *(float4*)&ws[r][c4 * 4] =
                *(const float4*)&W[(size_t)(k0 + r) * HDIM + c4 * 4];
        }
        __syncthreads();

#pragma unroll
        for (int kk = 0; kk < 32; kk++) {
            float4 w0 = *(float4*)&ws[kk][tx * 8];
            float4 w1 = *(float4*)&ws[kk][tx * 8 + 4];
            float wv[8] = {w0.x, w0.y, w0.z, w0.w, w1.x, w1.y, w1.z, w1.w};
#pragma unroll
            for (int i = 0; i < 4; i++) {
                float xv = xs[ty * 4 + i][kk];
#pragma unroll
                for (int j = 0; j < 8; j++) acc[i][j] += xv * wv[j];
            }
        }
        __syncthreads();
    }

#pragma unroll
    for (int i = 0; i < 4; i++) {
        int row = m0 + ty * 4 + i;
        float4 o0 = {acc[i][0], acc[i][1], acc[i][2], acc[i][3]};
        float4 o1 = {acc[i][4], acc[i][5], acc[i][6], acc[i][7]};
        *(float4*)&outp[(size_t)row * HDIM + tx * 8]     = o0;
        *(float4*)&outp[(size_t)row * HDIM + tx * 8 + 4] = o1;
    }
}

// ---------------------------------------------------------------------------
// Causal flash attention, fp32.
// Grid (32, 8): block handles BM=64 query rows of one batch. 256 threads.
// Warp w owns output rows w*8..w*8+7.
// S compute: lane = ry*16+cx; 4x4 microtile rows (w*8+ry*4+i), cols (cx*4+j).
// O update : lane owns cols lane*4..+3 of all 8 warp rows.
// ---------------------------------------------------------------------------
#define SMEM_FLOATS (64*128 + 64*129 + 64*128 + 64*64)
#define SMEM_BYTES  (SMEM_FLOATS * 4)

__global__ __launch_bounds__(256, 2) void attn_kernel(float* __restrict__ out)
{
    extern __shared__ float smem[];
    float* qs = smem;                 // [64][128]
    float* ks = qs + 64 * 128;        // [64][129]  (pad -> stride 129 ≡ 1 mod 32)
    float* vs = ks + 64 * 129;        // [64][128]
    float* ps = vs + 64 * 128;        // [64][64]

    const int ib   = (int)gridDim.x - 1 - (int)blockIdx.x;  // heavy tiles first
    const int b    = blockIdx.y;
    const int tid  = threadIdx.x;
    const int warp = tid >> 5;
    const int lane = tid & 31;
    const int ry   = lane >> 4;       // 0/1
    const int cx   = lane & 15;
    const int m0   = ib * BM;

    const float* qg = g_q + (size_t)b * TSEQ * HDIM;
    const float* kg = g_k + (size_t)b * TSEQ * HDIM;
    const float* vg = g_v + (size_t)b * TSEQ * HDIM;

    // load Q tile [64][128]
#pragma unroll
    for (int i = 0; i < 8; i++) {
        int f4 = tid + 256 * i;       // 0..2047
        int r  = f4 >> 5;
        int c4 = f4 & 31;
        *(float4*)&qs[r * 128 + c4 * 4] =
            *(const float4*)&qg[(size_t)(m0 + r) * HDIM + c4 * 4];
    }

    float o[8][4];
#pragma unroll
    for (int r = 0; r < 8; r++)
#pragma unroll
        for (int c = 0; c < 4; c++) o[r][c] = 0.f;

    float m_run[4], l_run[4];
#pragma unroll
    for (int i = 0; i < 4; i++) { m_run[i] = -INFINITY; l_run[i] = 0.f; }

    const int r0 = warp * 8 + ry * 4;   // S-rows this lane owns
    const int c0 = cx * 4;              // S-cols this lane owns
    const int oc = lane * 4;            // O-cols this lane owns

    for (int jb = 0; jb <= ib; jb++) {
        const int n0 = jb * BN;
        // load K (padded, scalar stores) and V (float4) tiles
#pragma unroll
        for (int i = 0; i < 8; i++) {
            int f4 = tid + 256 * i;
            int r  = f4 >> 5;
            int c4 = f4 & 31;
            float4 kv = *(const float4*)&kg[(size_t)(n0 + r) * HDIM + c4 * 4];
            ks[r * 129 + c4 * 4 + 0] = kv.x; ks[r * 129 + c4 * 4 + 1] = kv.y;
            ks[r * 129 + c4 * 4 + 2] = kv.z; ks[r * 129 + c4 * 4 + 3] = kv.w;
            *(float4*)&vs[r * 128 + c4 * 4] =
                *(const float4*)&vg[(size_t)(n0 + r) * HDIM + c4 * 4];
        }
        __syncthreads();

        // ---- S = Q K^T (4x4 microtile per lane) ----
        float s[4][4];
#pragma unroll
        for (int i = 0; i < 4; i++)
#pragma unroll
            for (int j = 0; j < 4; j++) s[i][j] = 0.f;

        for (int h = 0; h < 128; h += 4) {
            float4 qq[4];
#pragma unroll
            for (int i = 0; i < 4; i++)
                qq[i] = *(const float4*)&qs[(r0 + i) * 128 + h];
            const float* qf = (const float*)qq;
#pragma unroll
            for (int hh = 0; hh < 4; hh++) {
                float kv[4];
#pragma unroll
                for (int j = 0; j < 4; j++)
                    kv[j] = ks[(c0 + j) * 129 + h + hh];
#pragma unroll
                for (int i = 0; i < 4; i++)
#pragma unroll
                    for (int j = 0; j < 4; j++)
                        s[i][j] += qf[i * 4 + hh] * kv[j];
            }
        }

        // ---- scale + causal mask ----
        const bool diag = (jb == ib);
#pragma unroll
        for (int i = 0; i < 4; i++)
#pragma unroll
            for (int j = 0; j < 4; j++) {
                float v = s[i][j] * 0.03125f;   // 1/sqrt(1024)
                if (diag && (c0 + j > r0 + i)) v = -INFINITY;
                s[i][j] = v;
            }

        // ---- online softmax: row max/sum across 16 cx lanes ----
        float mnew[4], alpha[4];
#pragma unroll
        for (int i = 0; i < 4; i++) {
            float tm = fmaxf(fmaxf(s[i][0], s[i][1]), fmaxf(s[i][2], s[i][3]));
#pragma unroll
            for (int msk = 1; msk < 16; msk <<= 1)
                tm = fmaxf(tm, __shfl_xor_sync(0xffffffffu, tm, msk));
            mnew[i]  = fmaxf(m_run[i], tm);
            alpha[i] = __expf(m_run[i] - mnew[i]);
        }
#pragma unroll
        for (int i = 0; i < 4; i++) {
            float acc = 0.f;
#pragma unroll
            for (int j = 0; j < 4; j++) {
                s[i][j] = __expf(s[i][j] - mnew[i]);
                acc += s[i][j];
            }
#pragma unroll
            for (int msk = 1; msk < 16; msk <<= 1)
                acc += __shfl_xor_sync(0xffffffffu, acc, msk);
            l_run[i] = l_run[i] * alpha[i] + acc;
            m_run[i] = mnew[i];
        }

        // ---- stage P to smem ----
#pragma unroll
        for (int i = 0; i < 4; i++) {
            float4 pv = {s[i][0], s[i][1], s[i][2], s[i][3]};
            *(float4*)&ps[(r0 + i) * 64 + c0] = pv;
        }

        // exchange alphas so every lane knows all 8 warp-row alphas
        float a8[8];
#pragma unroll
        for (int i = 0; i < 4; i++) {
            a8[ry * 4 + i]       = alpha[i];
            a8[(1 ^ ry) * 4 + i] = __shfl_xor_sync(0xffffffffu, alpha[i], 16);
        }
        __syncthreads();

        // ---- O = O*alpha + P V ----
#pragma unroll
        for (int r = 0; r < 8; r++)
#pragma unroll
            for (int c = 0; c < 4; c++) o[r][c] *= a8[r];

#pragma unroll 4
        for (int j = 0; j < 64; j++) {
            float4 vv = *(float4*)&vs[j * 128 + oc];
#pragma unroll
            for (int r = 0; r < 8; r++) {
                float pr = ps[(warp * 8 + r) * 64 + j];   // broadcast
                o[r][0] += pr * vv.x; o[r][1] += pr * vv.y;
                o[r][2] += pr * vv.z; o[r][3] += pr * vv.w;
            }
        }
        __syncthreads();   // protect ks/vs/ps for next tile
    }

    // ---- finalize: divide by row sums, write out ----
    float l8[8];
#pragma unroll
    for (int i = 0; i < 4; i++) {
        l8[ry * 4 + i]       = l_run[i];
        l8[(1 ^ ry) * 4 + i] = __shfl_xor_sync(0xffffffffu, l_run[i], 16);
    }
#pragma unroll
    for (int r = 0; r < 8; r++) {
        float inv = 1.f / l8[r];
        int row = m0 + warp * 8 + r;
        float4 ov = {o[r][0] * inv, o[r][1] * inv, o[r][2] * inv, o[r][3] * inv};
        *(float4*)&out[((size_t)b * TSEQ + row) * HDIM + oc] = ov;
    }
}

// ---------------------------------------------------------------------------
extern "C" void kernel_launch(void* const* d_in, const int* in_sizes, int n_in,
                              void* d_out, int out_size)
{
    const float* x  = (const float*)d_in[0];
    const float* Wq = (const float*)d_in[1];
    const float* Wk = (const float*)d_in[2];
    const float* Wv = (const float*)d_in[3];
    float* out = (float*)d_out;

    cudaFuncSetAttribute(attn_kernel,
                         cudaFuncAttributeMaxDynamicSharedMemorySize, SMEM_BYTES);

    proj_kernel<<<dim3(BT_TOTAL / 64, 3), 256>>>(x, Wq, Wk, Wv);
    attn_kernel<<<dim3(TSEQ / BM, BATCH), 256, SMEM_BYTES>>>(out);
}

// round 7
// speedup vs baseline: 1.5549x; 1.5549x over previous
#include <cuda_runtime.h>
#include <math.h>
#include <stdint.h>

#define BATCH   8
#define TSEQ    2048
#define CDIM    1024
#define HDIM    128
#define BT_TOTAL (BATCH*TSEQ)   // 16384
#define BM      64
#define BN      64

// Scratch (no cudaMalloc allowed).
__device__ float g_q[BT_TOTAL * HDIM];
__device__ float g_k[BT_TOTAL * HDIM];
__device__ float g_v[BT_TOTAL * HDIM];
__device__ float g_wt[3 * HDIM * CDIM];   // K-major transposed weights [3][128][1024], tf32-rounded

// ---------------------------------------------------------------------------
// mma.sync tf32 helpers (baseline PTX — valid on .target sm_100)
// ---------------------------------------------------------------------------
// cvt.rna.tf32.f32 requires a .b32 destination (bit pattern), hence "=r".
__device__ __forceinline__ uint32_t f32_to_tf32_bits(float x) {
    uint32_t y;
    asm("cvt.rna.tf32.f32 %0, %1;" : "=r"(y) : "f"(x));
    return y;
}
__device__ __forceinline__ float to_tf32(float x) {
    return __uint_as_float(f32_to_tf32_bits(x));   // tf32 pattern is a valid f32
}

// D += A(16x8 row) * B(8x8 col). a[4], b[2] are tf32 bit patterns.
__device__ __forceinline__ void mma_tf32(float4& d, const uint32_t a[4], const uint32_t b[2]) {
    asm volatile(
        "mma.sync.aligned.m16n8k8.row.col.f32.tf32.tf32.f32 "
        "{%0,%1,%2,%3}, {%4,%5,%6,%7}, {%8,%9}, {%0,%1,%2,%3};"
        : "+f"(d.x), "+f"(d.y), "+f"(d.z), "+f"(d.w)
        : "r"(a[0]), "r"(a[1]), "r"(a[2]), "r"(a[3]), "r"(b[0]), "r"(b[1]));
}

// swizzled column for float index k (0..31) in a 32-float row r
#define SWZ(r, k) ((k) ^ (((r) & 7) << 2))

// ---------------------------------------------------------------------------
// Transpose W [1024][128] -> Wt [128][1024] (n-major rows, K cols) + tf32 round.
// ---------------------------------------------------------------------------
__global__ __launch_bounds__(256) void transpose_kernel(
    const float* __restrict__ Wq, const float* __restrict__ Wk,
    const float* __restrict__ Wv)
{
    __shared__ float t[32][33];
    const int z = blockIdx.z;
    const float* W = (z == 0) ? Wq : (z == 1 ? Wk : Wv);
    float* out = g_wt + (size_t)z * HDIM * CDIM;
    const int k0 = blockIdx.x * 32;   // K dim (1024)
    const int n0 = blockIdx.y * 32;   // N dim (128)
    const int c  = threadIdx.x & 31;
    const int rb = threadIdx.x >> 5;
#pragma unroll
    for (int i = 0; i < 4; i++) {
        int r = rb + i * 8;
        t[r][c] = W[(size_t)(k0 + r) * HDIM + n0 + c];
    }
    __syncthreads();
#pragma unroll
    for (int i = 0; i < 4; i++) {
        int r = rb + i * 8;
        out[(size_t)(n0 + r) * CDIM + k0 + c] = to_tf32(t[c][r]);
    }
}

// ---------------------------------------------------------------------------
// tf32 mma.sync projection GEMM.
// Grid (128, 3): block = 128 m-rows x 128 n (one output z per blockIdx.y).
// 4 warps, each 64m x 64n: acc = 4 m16-tiles x 8 n8-tiles x float4.
// K-chunk = 32, XOR-swizzled smem tiles -> conflict-free fragment LDS.
// ---------------------------------------------------------------------------
__global__ __launch_bounds__(128, 2) void proj_mma_kernel(const float* __restrict__ x)
{
    __shared__ float xs[128 * 32];
    __shared__ float ws[128 * 32];

    const int z = blockIdx.y;
    const float* wt = g_wt + (size_t)z * HDIM * CDIM;
    float* outp = (z == 0) ? g_q : (z == 1 ? g_k : g_v);

    const int m0   = blockIdx.x * 128;
    const int tid  = threadIdx.x;
    const int lane = tid & 31;
    const int warp = tid >> 5;
    const int wm   = (warp >> 1) * 64;   // warp m-offset within block
    const int wn   = (warp & 1) * 64;    // warp n-offset within block

    const int qr = lane >> 2;            // 0..7  fragment row group
    const int qc = lane & 3;             // 0..3  fragment col group

    float4 acc[4][8];
#pragma unroll
    for (int mt = 0; mt < 4; mt++)
#pragma unroll
        for (int nt = 0; nt < 8; nt++) acc[mt][nt] = make_float4(0.f, 0.f, 0.f, 0.f);

    for (int kc = 0; kc < 32; kc++) {
        // ---- fill tiles (128 rows x 32 floats each), tf32-round X here ----
#pragma unroll
        for (int i = 0; i < 8; i++) {
            int idx = tid + 128 * i;            // 0..1023
            int r   = idx >> 3;
            int c4  = idx & 7;
            int sc4 = c4 ^ (r & 7);             // float4-granular swizzle
            float4 xv = *(const float4*)&x[(size_t)(m0 + r) * CDIM + kc * 32 + c4 * 4];
            xv.x = to_tf32(xv.x); xv.y = to_tf32(xv.y);
            xv.z = to_tf32(xv.z); xv.w = to_tf32(xv.w);
            *(float4*)&xs[r * 32 + sc4 * 4] = xv;
            float4 wv = *(const float4*)&wt[(size_t)r * CDIM + kc * 32 + c4 * 4];
            *(float4*)&ws[r * 32 + sc4 * 4] = wv;   // already tf32-rounded
        }
        __syncthreads();

#pragma unroll
        for (int k8 = 0; k8 < 4; k8++) {
            const int kb = k8 * 8;
            // B fragments: 8 n8-tiles
            uint32_t bf[8][2];
#pragma unroll
            for (int nt = 0; nt < 8; nt++) {
                int n = wn + nt * 8 + qr;
                bf[nt][0] = __float_as_uint(ws[n * 32 + SWZ(n, kb + qc)]);
                bf[nt][1] = __float_as_uint(ws[n * 32 + SWZ(n, kb + qc + 4)]);
            }
#pragma unroll
            for (int mt = 0; mt < 4; mt++) {
                int r  = wm + mt * 16 + qr;
                int r8 = r + 8;
                uint32_t af[4];
                af[0] = __float_as_uint(xs[r  * 32 + SWZ(r,  kb + qc)]);
                af[1] = __float_as_uint(xs[r8 * 32 + SWZ(r8, kb + qc)]);
                af[2] = __float_as_uint(xs[r  * 32 + SWZ(r,  kb + qc + 4)]);
                af[3] = __float_as_uint(xs[r8 * 32 + SWZ(r8, kb + qc + 4)]);
#pragma unroll
                for (int nt = 0; nt < 8; nt++)
                    mma_tf32(acc[mt][nt], af, bf[nt]);
            }
        }
        __syncthreads();
    }

    // ---- epilogue: D fragment c0/c1 at (row, 2*qc), c2/c3 at (row+8) ----
#pragma unroll
    for (int mt = 0; mt < 4; mt++) {
        int row = m0 + wm + mt * 16 + qr;
#pragma unroll
        for (int nt = 0; nt < 8; nt++) {
            int col = wn + nt * 8 + 2 * qc;
            *(float2*)&outp[(size_t)row * HDIM + col] =
                make_float2(acc[mt][nt].x, acc[mt][nt].y);
            *(float2*)&outp[(size_t)(row + 8) * HDIM + col] =
                make_float2(acc[mt][nt].z, acc[mt][nt].w);
        }
    }
}

// ---------------------------------------------------------------------------
// Causal flash attention, fp32 (unchanged — known-good at 551us).
// ---------------------------------------------------------------------------
#define SMEM_FLOATS (64*128 + 64*129 + 64*128 + 64*64)
#define SMEM_BYTES  (SMEM_FLOATS * 4)

__global__ __launch_bounds__(256, 2) void attn_kernel(float* __restrict__ out)
{
    extern __shared__ float fsmem[];
    float* qs = fsmem;
    float* ks = qs + 64 * 128;
    float* vs = ks + 64 * 129;
    float* ps = vs + 64 * 128;

    const int ib   = (int)gridDim.x - 1 - (int)blockIdx.x;
    const int b    = blockIdx.y;
    const int tid  = threadIdx.x;
    const int warp = tid >> 5;
    const int lane = tid & 31;
    const int ry   = lane >> 4;
    const int cx   = lane & 15;
    const int m0   = ib * BM;

    const float* qg = g_q + (size_t)b * TSEQ * HDIM;
    const float* kg = g_k + (size_t)b * TSEQ * HDIM;
    const float* vg = g_v + (size_t)b * TSEQ * HDIM;

#pragma unroll
    for (int i = 0; i < 8; i++) {
        int f4 = tid + 256 * i;
        int r  = f4 >> 5;
        int c4 = f4 & 31;
        *(float4*)&qs[r * 128 + c4 * 4] =
            *(const float4*)&qg[(size_t)(m0 + r) * HDIM + c4 * 4];
    }

    float o[8][4];
#pragma unroll
    for (int r = 0; r < 8; r++)
#pragma unroll
        for (int c = 0; c < 4; c++) o[r][c] = 0.f;

    float m_run[4], l_run[4];
#pragma unroll
    for (int i = 0; i < 4; i++) { m_run[i] = -INFINITY; l_run[i] = 0.f; }

    const int r0 = warp * 8 + ry * 4;
    const int c0 = cx * 4;
    const int oc = lane * 4;

    for (int jb = 0; jb <= ib; jb++) {
        const int n0 = jb * BN;
#pragma unroll
        for (int i = 0; i < 8; i++) {
            int f4 = tid + 256 * i;
            int r  = f4 >> 5;
            int c4 = f4 & 31;
            float4 kv = *(const float4*)&kg[(size_t)(n0 + r) * HDIM + c4 * 4];
            ks[r * 129 + c4 * 4 + 0] = kv.x; ks[r * 129 + c4 * 4 + 1] = kv.y;
            ks[r * 129 + c4 * 4 + 2] = kv.z; ks[r * 129 + c4 * 4 + 3] = kv.w;
            *(float4*)&vs[r * 128 + c4 * 4] =
                *(const float4*)&vg[(size_t)(n0 + r) * HDIM + c4 * 4];
        }
        __syncthreads();

        float s[4][4];
#pragma unroll
        for (int i = 0; i < 4; i++)
#pragma unroll
            for (int j = 0; j < 4; j++) s[i][j] = 0.f;

        for (int h = 0; h < 128; h += 4) {
            float4 qq[4];
#pragma unroll
            for (int i = 0; i < 4; i++)
                qq[i] = *(const float4*)&qs[(r0 + i) * 128 + h];
            const float* qf = (const float*)qq;
#pragma unroll
            for (int hh = 0; hh < 4; hh++) {
                float kv[4];
#pragma unroll
                for (int j = 0; j < 4; j++)
                    kv[j] = ks[(c0 + j) * 129 + h + hh];
#pragma unroll
                for (int i = 0; i < 4; i++)
#pragma unroll
                    for (int j = 0; j < 4; j++)
                        s[i][j] += qf[i * 4 + hh] * kv[j];
            }
        }

        const bool diag = (jb == ib);
#pragma unroll
        for (int i = 0; i < 4; i++)
#pragma unroll
            for (int j = 0; j < 4; j++) {
                float v = s[i][j] * 0.03125f;
                if (diag && (c0 + j > r0 + i)) v = -INFINITY;
                s[i][j] = v;
            }

        float mnew[4], alpha[4];
#pragma unroll
        for (int i = 0; i < 4; i++) {
            float tm = fmaxf(fmaxf(s[i][0], s[i][1]), fmaxf(s[i][2], s[i][3]));
#pragma unroll
            for (int msk = 1; msk < 16; msk <<= 1)
                tm = fmaxf(tm, __shfl_xor_sync(0xffffffffu, tm, msk));
            mnew[i]  = fmaxf(m_run[i], tm);
            alpha[i] = __expf(m_run[i] - mnew[i]);
        }
#pragma unroll
        for (int i = 0; i < 4; i++) {
            float acc = 0.f;
#pragma unroll
            for (int j = 0; j < 4; j++) {
                s[i][j] = __expf(s[i][j] - mnew[i]);
                acc += s[i][j];
            }
#pragma unroll
            for (int msk = 1; msk < 16; msk <<= 1)
                acc += __shfl_xor_sync(0xffffffffu, acc, msk);
            l_run[i] = l_run[i] * alpha[i] + acc;
            m_run[i] = mnew[i];
        }

#pragma unroll
        for (int i = 0; i < 4; i++) {
            float4 pv = {s[i][0], s[i][1], s[i][2], s[i][3]};
            *(float4*)&ps[(r0 + i) * 64 + c0] = pv;
        }

        float a8[8];
#pragma unroll
        for (int i = 0; i < 4; i++) {
            a8[ry * 4 + i]       = alpha[i];
            a8[(1 ^ ry) * 4 + i] = __shfl_xor_sync(0xffffffffu, alpha[i], 16);
        }
        __syncthreads();

#pragma unroll
        for (int r = 0; r < 8; r++)
#pragma unroll
            for (int c = 0; c < 4; c++) o[r][c] *= a8[r];

#pragma unroll 4
        for (int j = 0; j < 64; j++) {
            float4 vv = *(float4*)&vs[j * 128 + oc];
#pragma unroll
            for (int r = 0; r < 8; r++) {
                float pr = ps[(warp * 8 + r) * 64 + j];
                o[r][0] += pr * vv.x; o[r][1] += pr * vv.y;
                o[r][2] += pr * vv.z; o[r][3] += pr * vv.w;
            }
        }
        __syncthreads();
    }

    float l8[8];
#pragma unroll
    for (int i = 0; i < 4; i++) {
        l8[ry * 4 + i]       = l_run[i];
        l8[(1 ^ ry) * 4 + i] = __shfl_xor_sync(0xffffffffu, l_run[i], 16);
    }
#pragma unroll
    for (int r = 0; r < 8; r++) {
        float inv = 1.f / l8[r];
        int row = m0 + warp * 8 + r;
        float4 ov = {o[r][0] * inv, o[r][1] * inv, o[r][2] * inv, o[r][3] * inv};
        *(float4*)&out[((size_t)b * TSEQ + row) * HDIM + oc] = ov;
    }
}

// ---------------------------------------------------------------------------
extern "C" void kernel_launch(void* const* d_in, const int* in_sizes, int n_in,
                              void* d_out, int out_size)
{
    const float* x  = (const float*)d_in[0];
    const float* Wq = (const float*)d_in[1];
    const float* Wk = (const float*)d_in[2];
    const float* Wv = (const float*)d_in[3];
    float* out = (float*)d_out;

    cudaFuncSetAttribute(attn_kernel,
                         cudaFuncAttributeMaxDynamicSharedMemorySize, SMEM_BYTES);

    transpose_kernel<<<dim3(32, 4, 3), 256>>>(Wq, Wk, Wv);
    proj_mma_kernel<<<dim3(BT_TOTAL / 128, 3), 128>>>(x);
    attn_kernel<<<dim3(TSEQ / BM, BATCH), 256, SMEM_BYTES>>>(out);
}

// round 10
// speedup vs baseline: 3.3222x; 2.1366x over previous
#include <cuda_runtime.h>
#include <math.h>
#include <stdint.h>

#define BATCH   8
#define TSEQ    2048
#define CDIM    1024
#define HDIM    128
#define BT_TOTAL (BATCH*TSEQ)   // 16384
#define BM      64
#define BN      64
#define NTILES  (TSEQ/BM)       // 32

// Scratch (no cudaMalloc allowed).
__device__ float g_q[BT_TOTAL * HDIM];
__device__ float g_k[BT_TOTAL * HDIM];
__device__ float g_v[BT_TOTAL * HDIM];
__device__ float g_wt[3 * HDIM * CDIM];   // K-major transposed weights, tf32-rounded

// ---------------------------------------------------------------------------
// mma.sync tf32 helpers (baseline PTX — valid on .target sm_100)
// ---------------------------------------------------------------------------
__device__ __forceinline__ uint32_t f32_to_tf32_bits(float x) {
    uint32_t y;
    asm("cvt.rna.tf32.f32 %0, %1;" : "=r"(y) : "f"(x));
    return y;
}
__device__ __forceinline__ float to_tf32(float x) {
    return __uint_as_float(f32_to_tf32_bits(x));
}

// D += A(16x8 row) * B(8x8 col).
__device__ __forceinline__ void mma_tf32(float4& d, const uint32_t a[4], const uint32_t b[2]) {
    asm volatile(
        "mma.sync.aligned.m16n8k8.row.col.f32.tf32.tf32.f32 "
        "{%0,%1,%2,%3}, {%4,%5,%6,%7}, {%8,%9}, {%0,%1,%2,%3};"
        : "+f"(d.x), "+f"(d.y), "+f"(d.z), "+f"(d.w)
        : "r"(a[0]), "r"(a[1]), "r"(a[2]), "r"(a[3]), "r"(b[0]), "r"(b[1]));
}

// swizzled column for float index k (0..31) in a 32-float row r (proj tiles)
#define SWZ(r, k) ((k) ^ (((r) & 7) << 2))
// swizzled float index for 128-float rows: per-32-chunk XOR swizzle
#define FIDX(r, k) ((r)*128 + ((k) & ~31) + ((((k) & 31) ^ (((r) & 7) << 2))))

// ---------------------------------------------------------------------------
// Transpose W [1024][128] -> Wt [128][1024] (K-major) + tf32 round.
// ---------------------------------------------------------------------------
__global__ __launch_bounds__(256) void transpose_kernel(
    const float* __restrict__ Wq, const float* __restrict__ Wk,
    const float* __restrict__ Wv)
{
    __shared__ float t[32][33];
    const int z = blockIdx.z;
    const float* W = (z == 0) ? Wq : (z == 1 ? Wk : Wv);
    float* out = g_wt + (size_t)z * HDIM * CDIM;
    const int k0 = blockIdx.x * 32;
    const int n0 = blockIdx.y * 32;
    const int c  = threadIdx.x & 31;
    const int rb = threadIdx.x >> 5;
#pragma unroll
    for (int i = 0; i < 4; i++) {
        int r = rb + i * 8;
        t[r][c] = W[(size_t)(k0 + r) * HDIM + n0 + c];
    }
    __syncthreads();
#pragma unroll
    for (int i = 0; i < 4; i++) {
        int r = rb + i * 8;
        out[(size_t)(n0 + r) * CDIM + k0 + c] = to_tf32(t[c][r]);
    }
}

// ---------------------------------------------------------------------------
// tf32 mma.sync projection GEMM (validated R7). Epilogue rounds the
// q/k/v outputs to tf32 so the attention kernel needs no cvt in its hot loop.
// ---------------------------------------------------------------------------
__global__ __launch_bounds__(128, 2) void proj_mma_kernel(const float* __restrict__ x)
{
    __shared__ float xs[128 * 32];
    __shared__ float ws[128 * 32];

    const int z = blockIdx.y;
    const float* wt = g_wt + (size_t)z * HDIM * CDIM;
    float* outp = (z == 0) ? g_q : (z == 1 ? g_k : g_v);

    const int m0   = blockIdx.x * 128;
    const int tid  = threadIdx.x;
    const int lane = tid & 31;
    const int warp = tid >> 5;
    const int wm   = (warp >> 1) * 64;
    const int wn   = (warp & 1) * 64;
    const int qr   = lane >> 2;
    const int qc   = lane & 3;

    float4 acc[4][8];
#pragma unroll
    for (int mt = 0; mt < 4; mt++)
#pragma unroll
        for (int nt = 0; nt < 8; nt++) acc[mt][nt] = make_float4(0.f, 0.f, 0.f, 0.f);

    for (int kc = 0; kc < 32; kc++) {
#pragma unroll
        for (int i = 0; i < 8; i++) {
            int idx = tid + 128 * i;
            int r   = idx >> 3;
            int c4  = idx & 7;
            int sc4 = c4 ^ (r & 7);
            float4 xv = *(const float4*)&x[(size_t)(m0 + r) * CDIM + kc * 32 + c4 * 4];
            xv.x = to_tf32(xv.x); xv.y = to_tf32(xv.y);
            xv.z = to_tf32(xv.z); xv.w = to_tf32(xv.w);
            *(float4*)&xs[r * 32 + sc4 * 4] = xv;
            float4 wv = *(const float4*)&wt[(size_t)r * CDIM + kc * 32 + c4 * 4];
            *(float4*)&ws[r * 32 + sc4 * 4] = wv;
        }
        __syncthreads();

#pragma unroll
        for (int k8 = 0; k8 < 4; k8++) {
            const int kb = k8 * 8;
            uint32_t bf[8][2];
#pragma unroll
            for (int nt = 0; nt < 8; nt++) {
                int n = wn + nt * 8 + qr;
                bf[nt][0] = __float_as_uint(ws[n * 32 + SWZ(n, kb + qc)]);
                bf[nt][1] = __float_as_uint(ws[n * 32 + SWZ(n, kb + qc + 4)]);
            }
#pragma unroll
            for (int mt = 0; mt < 4; mt++) {
                int r  = wm + mt * 16 + qr;
                int r8 = r + 8;
                uint32_t af[4];
                af[0] = __float_as_uint(xs[r  * 32 + SWZ(r,  kb + qc)]);
                af[1] = __float_as_uint(xs[r8 * 32 + SWZ(r8, kb + qc)]);
                af[2] = __float_as_uint(xs[r  * 32 + SWZ(r,  kb + qc + 4)]);
                af[3] = __float_as_uint(xs[r8 * 32 + SWZ(r8, kb + qc + 4)]);
#pragma unroll
                for (int nt = 0; nt < 8; nt++)
                    mma_tf32(acc[mt][nt], af, bf[nt]);
            }
        }
        __syncthreads();
    }

    // epilogue: tf32-round q/k/v (consumed only by the tf32 attention kernel)
#pragma unroll
    for (int mt = 0; mt < 4; mt++) {
        int row = m0 + wm + mt * 16 + qr;
#pragma unroll
        for (int nt = 0; nt < 8; nt++) {
            int col = wn + nt * 8 + 2 * qc;
            *(float2*)&outp[(size_t)row * HDIM + col] =
                make_float2(to_tf32(acc[mt][nt].x), to_tf32(acc[mt][nt].y));
            *(float2*)&outp[(size_t)(row + 8) * HDIM + col] =
                make_float2(to_tf32(acc[mt][nt].z), to_tf32(acc[mt][nt].w));
        }
    }
}

// ---------------------------------------------------------------------------
// tf32 mma.sync causal flash attention — STATIC grid (32, 8), one item/CTA.
// 256 CTAs, 2/SM resident -> single wave; no work queue needed.
// CTA = (ib, b): 64 query rows. Inner loop over BN=64 kv tiles.
// Warp w owns m-strip rows [w*16, w*16+16).
// smem: qs[64][128] swz | kp[64][128] swz (K; reused for P stride 68) |
//       vs[64][136] pad. Total 100352 B -> 2 CTAs/SM.
// ---------------------------------------------------------------------------
#define ATT_QS   0
#define ATT_KP   (64*128)
#define ATT_VS   (2*64*128)
#define ATT_SMEM_BYTES ((2*64*128 + 64*136) * 4)   // 100352
#define PSTR 68
#define VSTR 136

__global__ __launch_bounds__(128, 2) void attn_kernel(float* __restrict__ out)
{
    extern __shared__ float sm[];
    float* qs = sm + ATT_QS;
    float* kp = sm + ATT_KP;    // K tile; overwritten by P after S phase
    float* vs = sm + ATT_VS;

    const int tid  = threadIdx.x;
    const int warp = tid >> 5;
    const int lane = tid & 31;
    const int qr   = lane >> 2;   // 0..7
    const int qc   = lane & 3;    // 0..3
    const int wm   = warp * 16;   // warp m-strip

    const int ib = blockIdx.x;
    const int b  = blockIdx.y;
    const int m0 = ib * BM;

    const float* qg = g_q + (size_t)b * TSEQ * HDIM;
    const float* kg = g_k + (size_t)b * TSEQ * HDIM;
    const float* vg = g_v + (size_t)b * TSEQ * HDIM;

    // ---- load Q tile [64][128], swizzled ----
#pragma unroll
    for (int i = 0; i < 16; i++) {
        int idx = tid + 128 * i;       // 0..2047 float4s
        int r   = idx >> 5;
        int c4  = idx & 31;
        int sc4 = (c4 & ~7) | ((c4 & 7) ^ (r & 7));
        *(float4*)&qs[r * 128 + sc4 * 4] =
            *(const float4*)&qg[(size_t)(m0 + r) * HDIM + c4 * 4];
    }

    // O fragments: 16 n8-tiles covering h = 0..127 for rows wm+qr, wm+qr+8
    float4 o[16];
#pragma unroll
    for (int nt = 0; nt < 16; nt++) o[nt] = make_float4(0.f, 0.f, 0.f, 0.f);
    float m0r = -INFINITY, m1r = -INFINITY, l0r = 0.f, l1r = 0.f;

    for (int jb = 0; jb <= ib; jb++) {
        const int n0 = jb * BN;
        __syncthreads();   // prev iter PV / Q-load complete before overwrite
        // ---- load K (swizzled) and V (padded stride 136) ----
#pragma unroll
        for (int i = 0; i < 16; i++) {
            int idx = tid + 128 * i;
            int r   = idx >> 5;
            int c4  = idx & 31;
            int sc4 = (c4 & ~7) | ((c4 & 7) ^ (r & 7));
            *(float4*)&kp[r * 128 + sc4 * 4] =
                *(const float4*)&kg[(size_t)(n0 + r) * HDIM + c4 * 4];
            *(float4*)&vs[r * VSTR + c4 * 4] =
                *(const float4*)&vg[(size_t)(n0 + r) * HDIM + c4 * 4];
        }
        __syncthreads();

        // ---- S = Q K^T : warp strip 16 x 64, k = 128 ----
        float4 sacc[8];
#pragma unroll
        for (int nt = 0; nt < 8; nt++) sacc[nt] = make_float4(0.f, 0.f, 0.f, 0.f);
#pragma unroll
        for (int k8 = 0; k8 < 16; k8++) {
            const int kb = k8 * 8;
            uint32_t af[4];
            af[0] = __float_as_uint(qs[FIDX(wm + qr,     kb + qc)]);
            af[1] = __float_as_uint(qs[FIDX(wm + qr + 8, kb + qc)]);
            af[2] = __float_as_uint(qs[FIDX(wm + qr,     kb + qc + 4)]);
            af[3] = __float_as_uint(qs[FIDX(wm + qr + 8, kb + qc + 4)]);
#pragma unroll
            for (int nt = 0; nt < 8; nt++) {
                uint32_t bf[2];
                bf[0] = __float_as_uint(kp[FIDX(nt * 8 + qr, kb + qc)]);
                bf[1] = __float_as_uint(kp[FIDX(nt * 8 + qr, kb + qc + 4)]);
                mma_tf32(sacc[nt], af, bf);
            }
        }

        // ---- scale + causal mask ----
        const bool diag = (jb == ib);
        const int gr0 = m0 + wm + qr, gr1 = gr0 + 8;
#pragma unroll
        for (int nt = 0; nt < 8; nt++) {
            int gc = n0 + nt * 8 + 2 * qc;
            sacc[nt].x *= 0.03125f; sacc[nt].y *= 0.03125f;
            sacc[nt].z *= 0.03125f; sacc[nt].w *= 0.03125f;
            if (diag) {
                if (gc     > gr0) sacc[nt].x = -INFINITY;
                if (gc + 1 > gr0) sacc[nt].y = -INFINITY;
                if (gc     > gr1) sacc[nt].z = -INFINITY;
                if (gc + 1 > gr1) sacc[nt].w = -INFINITY;
            }
        }

        // ---- online softmax (rows qr, qr+8 of strip) ----
        float mx0 = -INFINITY, mx1 = -INFINITY;
#pragma unroll
        for (int nt = 0; nt < 8; nt++) {
            mx0 = fmaxf(mx0, fmaxf(sacc[nt].x, sacc[nt].y));
            mx1 = fmaxf(mx1, fmaxf(sacc[nt].z, sacc[nt].w));
        }
        mx0 = fmaxf(mx0, __shfl_xor_sync(0xffffffffu, mx0, 1));
        mx0 = fmaxf(mx0, __shfl_xor_sync(0xffffffffu, mx0, 2));
        mx1 = fmaxf(mx1, __shfl_xor_sync(0xffffffffu, mx1, 1));
        mx1 = fmaxf(mx1, __shfl_xor_sync(0xffffffffu, mx1, 2));
        const float mn0 = fmaxf(m0r, mx0), mn1 = fmaxf(m1r, mx1);
        const float a0  = __expf(m0r - mn0), a1 = __expf(m1r - mn1);
        float s0 = 0.f, s1 = 0.f;
#pragma unroll
        for (int nt = 0; nt < 8; nt++) {
            sacc[nt].x = __expf(sacc[nt].x - mn0);
            sacc[nt].y = __expf(sacc[nt].y - mn0);
            sacc[nt].z = __expf(sacc[nt].z - mn1);
            sacc[nt].w = __expf(sacc[nt].w - mn1);
            s0 += sacc[nt].x + sacc[nt].y;
            s1 += sacc[nt].z + sacc[nt].w;
        }
        s0 += __shfl_xor_sync(0xffffffffu, s0, 1);
        s0 += __shfl_xor_sync(0xffffffffu, s0, 2);
        s1 += __shfl_xor_sync(0xffffffffu, s1, 1);
        s1 += __shfl_xor_sync(0xffffffffu, s1, 2);
        l0r = l0r * a0 + s0;  m0r = mn0;
        l1r = l1r * a1 + s1;  m1r = mn1;

        __syncthreads();   // all warps done reading K before P overwrites it

        // ---- store P (tf32) into K buffer, stride 68 ----
#pragma unroll
        for (int nt = 0; nt < 8; nt++) {
            int col = nt * 8 + 2 * qc;
            *(float2*)&kp[(wm + qr) * PSTR + col] =
                make_float2(to_tf32(sacc[nt].x), to_tf32(sacc[nt].y));
            *(float2*)&kp[(wm + qr + 8) * PSTR + col] =
                make_float2(to_tf32(sacc[nt].z), to_tf32(sacc[nt].w));
        }
        __syncwarp();

        // ---- rescale O, then O += P V ----
#pragma unroll
        for (int nt = 0; nt < 16; nt++) {
            o[nt].x *= a0; o[nt].y *= a0;
            o[nt].z *= a1; o[nt].w *= a1;
        }
#pragma unroll
        for (int kt = 0; kt < 8; kt++) {
            const int kb = kt * 8;
            uint32_t af[4];
            af[0] = __float_as_uint(kp[(wm + qr)     * PSTR + kb + qc]);
            af[1] = __float_as_uint(kp[(wm + qr + 8) * PSTR + kb + qc]);
            af[2] = __float_as_uint(kp[(wm + qr)     * PSTR + kb + qc + 4]);
            af[3] = __float_as_uint(kp[(wm + qr + 8) * PSTR + kb + qc + 4]);
#pragma unroll
            for (int nt = 0; nt < 16; nt++) {
                uint32_t bf[2];
                bf[0] = __float_as_uint(vs[(kb + qc)     * VSTR + nt * 8 + qr]);
                bf[1] = __float_as_uint(vs[(kb + qc + 4) * VSTR + nt * 8 + qr]);
                mma_tf32(o[nt], af, bf);
            }
        }
    }

    // ---- finalize: divide by row sums, write out ----
    const float i0 = 1.f / l0r, i1 = 1.f / l1r;
    const int r0 = m0 + wm + qr, r1 = r0 + 8;
#pragma unroll
    for (int nt = 0; nt < 16; nt++) {
        int col = nt * 8 + 2 * qc;
        *(float2*)&out[((size_t)b * TSEQ + r0) * HDIM + col] =
            make_float2(o[nt].x * i0, o[nt].y * i0);
        *(float2*)&out[((size_t)b * TSEQ + r1) * HDIM + col] =
            make_float2(o[nt].z * i1, o[nt].w * i1);
    }
}

// ---------------------------------------------------------------------------
extern "C" void kernel_launch(void* const* d_in, const int* in_sizes, int n_in,
                              void* d_out, int out_size)
{
    const float* x  = (const float*)d_in[0];
    const float* Wq = (const float*)d_in[1];
    const float* Wk = (const float*)d_in[2];
    const float* Wv = (const float*)d_in[3];
    float* out = (float*)d_out;

    cudaFuncSetAttribute(attn_kernel,
                         cudaFuncAttributeMaxDynamicSharedMemorySize, ATT_SMEM_BYTES);

    transpose_kernel<<<dim3(32, 4, 3), 256>>>(Wq, Wk, Wv);
    proj_mma_kernel<<<dim3(BT_TOTAL / 128, 3), 128>>>(x);
    attn_kernel<<<dim3(NTILES, BATCH), 128, ATT_SMEM_BYTES>>>(out);
}

// round 11
// speedup vs baseline: 4.6367x; 1.3957x over previous
#include <cuda_runtime.h>
#include <math.h>
#include <stdint.h>

#define BATCH   8
#define TSEQ    2048
#define CDIM    1024
#define HDIM    128
#define BT_TOTAL (BATCH*TSEQ)   // 16384
#define BM      128
#define BN      64
#define NQT     (TSEQ/BM)       // 16

// Scratch (no cudaMalloc allowed).
__device__ float g_q[BT_TOTAL * HDIM];
__device__ float g_k[BT_TOTAL * HDIM];
__device__ float g_v[BT_TOTAL * HDIM];
__device__ float g_wt[3 * HDIM * CDIM];   // K-major transposed weights, tf32-rounded

// ---------------------------------------------------------------------------
// PTX helpers (baseline PTX — valid on .target sm_100)
// ---------------------------------------------------------------------------
__device__ __forceinline__ uint32_t f32_to_tf32_bits(float x) {
    uint32_t y;
    asm("cvt.rna.tf32.f32 %0, %1;" : "=r"(y) : "f"(x));
    return y;
}
__device__ __forceinline__ float to_tf32(float x) {
    return __uint_as_float(f32_to_tf32_bits(x));
}

// D += A(16x8 row) * B(8x8 col).
__device__ __forceinline__ void mma_tf32(float4& d, const uint32_t a[4], const uint32_t b[2]) {
    asm volatile(
        "mma.sync.aligned.m16n8k8.row.col.f32.tf32.tf32.f32 "
        "{%0,%1,%2,%3}, {%4,%5,%6,%7}, {%8,%9}, {%0,%1,%2,%3};"
        : "+f"(d.x), "+f"(d.y), "+f"(d.z), "+f"(d.w)
        : "r"(a[0]), "r"(a[1]), "r"(a[2]), "r"(a[3]), "r"(b[0]), "r"(b[1]));
}

__device__ __forceinline__ uint32_t smem_u32(const void* p) {
    uint32_t a;
    asm("{ .reg .u64 t; cvta.to.shared.u64 t, %1; cvt.u32.u64 %0, t; }"
        : "=r"(a) : "l"(p));
    return a;
}
__device__ __forceinline__ void cp_async16(uint32_t dst, const void* src) {
    asm volatile("cp.async.cg.shared.global [%0], [%1], 16;" :: "r"(dst), "l"(src));
}
#define CP_COMMIT()  asm volatile("cp.async.commit_group;" ::: "memory")
#define CP_WAIT(n)   asm volatile("cp.async.wait_group %0;" :: "n"(n) : "memory")

// swizzles
#define SWZ(r, k)  ((k) ^ (((r) & 7) << 2))                                   // 32-float rows
#define FIDX(r, k) ((r)*128 + ((k) & ~31) + ((((k) & 31) ^ (((r) & 7) << 2))))// 128-float rows
#define PSW(r, c)  ((r)*64 + ((c) ^ (((r) & 7) << 2)))                        // 64-float P rows

// ---------------------------------------------------------------------------
// Transpose W [1024][128] -> Wt [128][1024] (K-major) + tf32 rna round.
// ---------------------------------------------------------------------------
__global__ __launch_bounds__(256) void transpose_kernel(
    const float* __restrict__ Wq, const float* __restrict__ Wk,
    const float* __restrict__ Wv)
{
    __shared__ float t[32][33];
    const int z = blockIdx.z;
    const float* W = (z == 0) ? Wq : (z == 1 ? Wk : Wv);
    float* out = g_wt + (size_t)z * HDIM * CDIM;
    const int k0 = blockIdx.x * 32;
    const int n0 = blockIdx.y * 32;
    const int c  = threadIdx.x & 31;
    const int rb = threadIdx.x >> 5;
#pragma unroll
    for (int i = 0; i < 4; i++) {
        int r = rb + i * 8;
        t[r][c] = W[(size_t)(k0 + r) * HDIM + n0 + c];
    }
    __syncthreads();
#pragma unroll
    for (int i = 0; i < 4; i++) {
        int r = rb + i * 8;
        out[(size_t)(n0 + r) * CDIM + k0 + c] = to_tf32(t[c][r]);
    }
}

// ---------------------------------------------------------------------------
// tf32 mma.sync projection GEMM, cp.async double-buffered.
// Grid (128, 3), 128 thr, 4 warps (64x64 each), K-chunk 32.
// Dynamic smem: xs[2][128*32] | ws[2][128*32] = 64 KB -> 2 CTAs/SM.
// X copied raw (HMMA truncates to tf32); W pre-rounded rna.
// ---------------------------------------------------------------------------
#define PROJ_SMEM_BYTES (4 * 128 * 32 * 4)   // 65536

__global__ __launch_bounds__(128, 2) void proj_mma_kernel(const float* __restrict__ x)
{
    extern __shared__ float psm[];
    float* xs = psm;                 // [2][4096]
    float* ws = psm + 2 * 4096;      // [2][4096]
    const uint32_t xs_a = smem_u32(xs);
    const uint32_t ws_a = smem_u32(ws);

    const int z = blockIdx.y;
    const float* wt = g_wt + (size_t)z * HDIM * CDIM;
    float* outp = (z == 0) ? g_q : (z == 1 ? g_k : g_v);

    const int m0   = blockIdx.x * 128;
    const int tid  = threadIdx.x;
    const int lane = tid & 31;
    const int warp = tid >> 5;
    const int wm   = (warp >> 1) * 64;
    const int wn   = (warp & 1) * 64;
    const int qr   = lane >> 2;
    const int qc   = lane & 3;

    // stage loader: 1024 float4 per tile, 8 per thread each for X and W
    auto load_stage = [&](int buf, int kc) {
#pragma unroll
        for (int i = 0; i < 8; i++) {
            int idx = tid + 128 * i;
            int r   = idx >> 3;
            int c4  = idx & 7;
            int sc4 = c4 ^ (r & 7);
            cp_async16(xs_a + (buf * 4096 + r * 32 + sc4 * 4) * 4,
                       &x[(size_t)(m0 + r) * CDIM + kc * 32 + c4 * 4]);
            cp_async16(ws_a + (buf * 4096 + r * 32 + sc4 * 4) * 4,
                       &wt[(size_t)r * CDIM + kc * 32 + c4 * 4]);
        }
    };

    float4 acc[4][8];
#pragma unroll
    for (int mt = 0; mt < 4; mt++)
#pragma unroll
        for (int nt = 0; nt < 8; nt++) acc[mt][nt] = make_float4(0.f, 0.f, 0.f, 0.f);

    load_stage(0, 0);
    CP_COMMIT();

    for (int kc = 0; kc < 32; kc++) {
        const int cur = kc & 1;
        __syncthreads();                       // prev compute done before nxt overwrite
        if (kc + 1 < 32) { load_stage(cur ^ 1, kc + 1); CP_COMMIT(); CP_WAIT(1); }
        else             { CP_WAIT(0); }
        __syncthreads();

        const float* xb = xs + cur * 4096;
        const float* wb = ws + cur * 4096;
#pragma unroll
        for (int k8 = 0; k8 < 4; k8++) {
            const int kb = k8 * 8;
            uint32_t bf[8][2];
#pragma unroll
            for (int nt = 0; nt < 8; nt++) {
                int n = wn + nt * 8 + qr;
                bf[nt][0] = __float_as_uint(wb[n * 32 + SWZ(n, kb + qc)]);
                bf[nt][1] = __float_as_uint(wb[n * 32 + SWZ(n, kb + qc + 4)]);
            }
#pragma unroll
            for (int mt = 0; mt < 4; mt++) {
                int r  = wm + mt * 16 + qr;
                int r8 = r + 8;
                uint32_t af[4];
                af[0] = __float_as_uint(xb[r  * 32 + SWZ(r,  kb + qc)]);
                af[1] = __float_as_uint(xb[r8 * 32 + SWZ(r8, kb + qc)]);
                af[2] = __float_as_uint(xb[r  * 32 + SWZ(r,  kb + qc + 4)]);
                af[3] = __float_as_uint(xb[r8 * 32 + SWZ(r8, kb + qc + 4)]);
#pragma unroll
                for (int nt = 0; nt < 8; nt++)
                    mma_tf32(acc[mt][nt], af, bf[nt]);
            }
        }
    }

    // epilogue: tf32-round q/k/v (consumed only by the tf32 attention kernel)
#pragma unroll
    for (int mt = 0; mt < 4; mt++) {
        int row = m0 + wm + mt * 16 + qr;
#pragma unroll
        for (int nt = 0; nt < 8; nt++) {
            int col = wn + nt * 8 + 2 * qc;
            *(float2*)&outp[(size_t)row * HDIM + col] =
                make_float2(to_tf32(acc[mt][nt].x), to_tf32(acc[mt][nt].y));
            *(float2*)&outp[(size_t)(row + 8) * HDIM + col] =
                make_float2(to_tf32(acc[mt][nt].z), to_tf32(acc[mt][nt].w));
        }
    }
}

// ---------------------------------------------------------------------------
// tf32 mma.sync causal flash attention, cp.async double-buffered KV.
// Grid (16, 8), 256 thr, 8 warps, BM=128, BN=64, 1 CTA/SM (single wave).
// Warp w owns m-strip [w*16, w*16+16). KV tiles jb = 0 .. 2*ibx+1.
// smem (floats): qs[128*128] | kb[2][64*128] (K, reused for P stride-64 swz) |
//                vb[2][64*136]. Total 200704 B.
// ---------------------------------------------------------------------------
#define A_QS  0
#define A_KB0 16384
#define A_KB1 24576
#define A_VB0 32768
#define A_VB1 41472
#define ATT_SMEM_BYTES (50176 * 4)   // 200704
#define VSTR 136

__global__ __launch_bounds__(256, 1) void attn_kernel(float* __restrict__ out)
{
    extern __shared__ float sm[];
    const uint32_t sm_a = smem_u32(sm);

    const int tid  = threadIdx.x;
    const int warp = tid >> 5;
    const int lane = tid & 31;
    const int qr   = lane >> 2;   // 0..7
    const int qc   = lane & 3;    // 0..3
    const int wm   = warp * 16;   // warp m-strip (0..112)

    const int ibx = blockIdx.x;
    const int b   = blockIdx.y;
    const int m0  = ibx * BM;
    const int jbmax = 2 * ibx + 1;

    const float* qg = g_q + (size_t)b * TSEQ * HDIM;
    const float* kg = g_k + (size_t)b * TSEQ * HDIM;
    const float* vg = g_v + (size_t)b * TSEQ * HDIM;

    // KV stage loader: K 2048 f4 + V 2048 f4 -> 8+8 per thread
    auto load_kv = [&](int buf, int jb) {
        const int n0 = jb * BN;
        const int kbo = buf ? A_KB1 : A_KB0;
        const int vbo = buf ? A_VB1 : A_VB0;
#pragma unroll
        for (int i = 0; i < 8; i++) {
            int idx = tid + 256 * i;     // 0..2047
            int r   = idx >> 5;          // 0..63
            int c4  = idx & 31;
            int sc4 = (c4 & ~7) | ((c4 & 7) ^ (r & 7));
            cp_async16(sm_a + (kbo + r * 128 + sc4 * 4) * 4,
                       &kg[(size_t)(n0 + r) * HDIM + c4 * 4]);
            cp_async16(sm_a + (vbo + r * VSTR + c4 * 4) * 4,
                       &vg[(size_t)(n0 + r) * HDIM + c4 * 4]);
        }
    };

    // prologue: Q (16/thr) + KV stage 0, one commit group
#pragma unroll
    for (int i = 0; i < 16; i++) {
        int idx = tid + 256 * i;         // 0..4095
        int r   = idx >> 5;              // 0..127
        int c4  = idx & 31;
        int sc4 = (c4 & ~7) | ((c4 & 7) ^ (r & 7));
        cp_async16(sm_a + (A_QS + r * 128 + sc4 * 4) * 4,
                   &qg[(size_t)(m0 + r) * HDIM + c4 * 4]);
    }
    load_kv(0, 0);
    CP_COMMIT();

    const float* qs = sm + A_QS;

    float4 o[16];
#pragma unroll
    for (int nt = 0; nt < 16; nt++) o[nt] = make_float4(0.f, 0.f, 0.f, 0.f);
    float m0r = -INFINITY, m1r = -INFINITY, l0r = 0.f, l1r = 0.f;

    for (int jb = 0; jb <= jbmax; jb++) {
        const int cur = jb & 1;
        float* kp = sm + (cur ? A_KB1 : A_KB0);
        const float* vs = sm + (cur ? A_VB1 : A_VB0);
        const int n0 = jb * BN;

        __syncthreads();                 // prev iter's PV reads done
        if (jb < jbmax) { load_kv(cur ^ 1, jb + 1); CP_COMMIT(); CP_WAIT(1); }
        else            { CP_WAIT(0); }
        __syncthreads();

        // ---- S = Q K^T : warp strip 16 x 64, k = 128 ----
        float4 sacc[8];
#pragma unroll
        for (int nt = 0; nt < 8; nt++) sacc[nt] = make_float4(0.f, 0.f, 0.f, 0.f);
#pragma unroll
        for (int k8 = 0; k8 < 16; k8++) {
            const int kb = k8 * 8;
            uint32_t af[4];
            af[0] = __float_as_uint(qs[FIDX(wm + qr,     kb + qc)]);
            af[1] = __float_as_uint(qs[FIDX(wm + qr + 8, kb + qc)]);
            af[2] = __float_as_uint(qs[FIDX(wm + qr,     kb + qc + 4)]);
            af[3] = __float_as_uint(qs[FIDX(wm + qr + 8, kb + qc + 4)]);
#pragma unroll
            for (int nt = 0; nt < 8; nt++) {
                uint32_t bf[2];
                bf[0] = __float_as_uint(kp[FIDX(nt * 8 + qr, kb + qc)]);
                bf[1] = __float_as_uint(kp[FIDX(nt * 8 + qr, kb + qc + 4)]);
                mma_tf32(sacc[nt], af, bf);
            }
        }

        // ---- scale + causal mask (only last two KV tiles intersect diag) ----
        const bool diag = (jb >= 2 * ibx);
        const int gr0 = m0 + wm + qr, gr1 = gr0 + 8;
#pragma unroll
        for (int nt = 0; nt < 8; nt++) {
            int gc = n0 + nt * 8 + 2 * qc;
            sacc[nt].x *= 0.03125f; sacc[nt].y *= 0.03125f;
            sacc[nt].z *= 0.03125f; sacc[nt].w *= 0.03125f;
            if (diag) {
                if (gc     > gr0) sacc[nt].x = -INFINITY;
                if (gc + 1 > gr0) sacc[nt].y = -INFINITY;
                if (gc     > gr1) sacc[nt].z = -INFINITY;
                if (gc + 1 > gr1) sacc[nt].w = -INFINITY;
            }
        }

        // ---- online softmax ----
        float mx0 = -INFINITY, mx1 = -INFINITY;
#pragma unroll
        for (int nt = 0; nt < 8; nt++) {
            mx0 = fmaxf(mx0, fmaxf(sacc[nt].x, sacc[nt].y));
            mx1 = fmaxf(mx1, fmaxf(sacc[nt].z, sacc[nt].w));
        }
        mx0 = fmaxf(mx0, __shfl_xor_sync(0xffffffffu, mx0, 1));
        mx0 = fmaxf(mx0, __shfl_xor_sync(0xffffffffu, mx0, 2));
        mx1 = fmaxf(mx1, __shfl_xor_sync(0xffffffffu, mx1, 1));
        mx1 = fmaxf(mx1, __shfl_xor_sync(0xffffffffu, mx1, 2));
        const float mn0 = fmaxf(m0r, mx0), mn1 = fmaxf(m1r, mx1);
        const float a0  = __expf(m0r - mn0), a1 = __expf(m1r - mn1);
        float s0 = 0.f, s1 = 0.f;
#pragma unroll
        for (int nt = 0; nt < 8; nt++) {
            sacc[nt].x = __expf(sacc[nt].x - mn0);
            sacc[nt].y = __expf(sacc[nt].y - mn0);
            sacc[nt].z = __expf(sacc[nt].z - mn1);
            sacc[nt].w = __expf(sacc[nt].w - mn1);
            s0 += sacc[nt].x + sacc[nt].y;
            s1 += sacc[nt].z + sacc[nt].w;
        }
        s0 += __shfl_xor_sync(0xffffffffu, s0, 1);
        s0 += __shfl_xor_sync(0xffffffffu, s0, 2);
        s1 += __shfl_xor_sync(0xffffffffu, s1, 1);
        s1 += __shfl_xor_sync(0xffffffffu, s1, 2);
        l0r = l0r * a0 + s0;  m0r = mn0;
        l1r = l1r * a1 + s1;  m1r = mn1;

        __syncthreads();   // all warps done reading K before P overwrites it

        // ---- store P into K buffer: 64-float rows, XOR swizzle ----
#pragma unroll
        for (int nt = 0; nt < 8; nt++) {
            int col = nt * 8 + 2 * qc;
            *(float2*)&kp[PSW(wm + qr, col)] =
                make_float2(sacc[nt].x, sacc[nt].y);
            *(float2*)&kp[PSW(wm + qr + 8, col)] =
                make_float2(sacc[nt].z, sacc[nt].w);
        }
        __syncwarp();

        // ---- rescale O, then O += P V ----
#pragma unroll
        for (int nt = 0; nt < 16; nt++) {
            o[nt].x *= a0; o[nt].y *= a0;
            o[nt].z *= a1; o[nt].w *= a1;
        }
#pragma unroll
        for (int kt = 0; kt < 8; kt++) {
            const int kb = kt * 8;
            uint32_t af[4];
            af[0] = __float_as_uint(kp[PSW(wm + qr,     kb + qc)]);
            af[1] = __float_as_uint(kp[PSW(wm + qr + 8, kb + qc)]);
            af[2] = __float_as_uint(kp[PSW(wm + qr,     kb + qc + 4)]);
            af[3] = __float_as_uint(kp[PSW(wm + qr + 8, kb + qc + 4)]);
#pragma unroll
            for (int nt = 0; nt < 16; nt++) {
                uint32_t bf[2];
                bf[0] = __float_as_uint(vs[(kb + qc)     * VSTR + nt * 8 + qr]);
                bf[1] = __float_as_uint(vs[(kb + qc + 4) * VSTR + nt * 8 + qr]);
                mma_tf32(o[nt], af, bf);
            }
        }
    }

    // ---- finalize: divide by row sums, write out ----
    const float i0 = 1.f / l0r, i1 = 1.f / l1r;
    const int r0 = m0 + wm + qr, r1 = r0 + 8;
#pragma unroll
    for (int nt = 0; nt < 16; nt++) {
        int col = nt * 8 + 2 * qc;
        *(float2*)&out[((size_t)b * TSEQ + r0) * HDIM + col] =
            make_float2(o[nt].x * i0, o[nt].y * i0);
        *(float2*)&out[((size_t)b * TSEQ + r1) * HDIM + col] =
            make_float2(o[nt].z * i1, o[nt].w * i1);
    }
}

// ---------------------------------------------------------------------------
extern "C" void kernel_launch(void* const* d_in, const int* in_sizes, int n_in,
                              void* d_out, int out_size)
{
    const float* x  = (const float*)d_in[0];
    const float* Wq = (const float*)d_in[1];
    const float* Wk = (const float*)d_in[2];
    const float* Wv = (const float*)d_in[3];
    float* out = (float*)d_out;

    cudaFuncSetAttribute(proj_mma_kernel,
                         cudaFuncAttributeMaxDynamicSharedMemorySize, PROJ_SMEM_BYTES);
    cudaFuncSetAttribute(attn_kernel,
                         cudaFuncAttributeMaxDynamicSharedMemorySize, ATT_SMEM_BYTES);

    transpose_kernel<<<dim3(32, 4, 3), 256>>>(Wq, Wk, Wv);
    proj_mma_kernel<<<dim3(BT_TOTAL / 128, 3), 128, PROJ_SMEM_BYTES>>>(x);
    attn_kernel<<<dim3(NQT, BATCH), 256, ATT_SMEM_BYTES>>>(out);
}